// round 1
// baseline (speedup 1.0000x reference)
#include <cuda_runtime.h>
#include <cuda_bf16.h>
#include <cstdint>

// Problem constants
#define NB 64            // batch
#define NS 1024          // seq len
#define NH 512           // hidden
#define NM (NB*NS)       // 65536 rows
#define NK 512
#define NN 512
#define WSTRIDE (512*512)

// ---------------- scratch (device globals; no allocs allowed) ----------------
__device__ float g_z  [ (size_t)NM*NN ];
__device__ float g_ag [ (size_t)NM*NN ];
__device__ float g_rh [ (size_t)NM*NN ];
__device__ float g_h0b[ (size_t)NM*NN ];
__device__ float g_h1b[ (size_t)NM*NN ];
__device__ float g_h2b[ (size_t)NM*NN ];
__device__ float g_hz [ NB*NH ];
__device__ float g_hr [ NB*NH ];
__device__ float g_h0c[ NB*NH ];
__device__ float g_wz [ 2*WSTRIDE ];
__device__ float g_wr [ 2*WSTRIDE ];

// Hz0 = h0 @ Wzh[0], Hr0 = h0 @ Wrh[0]; also compact h0 into contiguous [B,512].
__global__ void k_pre(const float* __restrict__ hs,
                      const float* __restrict__ Wzh0,
                      const float* __restrict__ Wrh0,
                      float* __restrict__ hz, float* __restrict__ hr,
                      float* __restrict__ h0c) {
    __shared__ float h0s[512];
    int b = blockIdx.x;
    int n = threadIdx.x;
    float h0v = hs[b*3*NH + n];   // hidden_state[b, layer 0, n]
    h0s[n] = h0v;
    if (blockIdx.y == 0) h0c[b*NH + n] = h0v;
    __syncthreads();
    const float* W = blockIdx.y ? Wrh0 : Wzh0;
    float acc = 0.f;
    #pragma unroll 8
    for (int k = 0; k < 512; k++) acc = fmaf(h0s[k], W[k*512 + n], acc);
    (blockIdx.y ? hr : hz)[b*NH + n] = acc;
}

// Combined weights for layers 1,2:  Wz' = Wzx[l]+Wzh[l], Wr' = Wrx[l]+Wrh[l]
__global__ void k_comb(const float* __restrict__ Wzx, const float* __restrict__ Wzh,
                       const float* __restrict__ Wrx, const float* __restrict__ Wrh,
                       float* __restrict__ wz, float* __restrict__ wr) {
    int i = blockIdx.x * blockDim.x + threadIdx.x;
    if (i >= 2*WSTRIDE) return;
    int l = i / WSTRIDE + 1;
    int off = i - (l-1)*WSTRIDE;
    wz[i] = Wzx[(size_t)l*WSTRIDE + off] + Wzh[(size_t)l*WSTRIDE + off];
    wr[i] = Wrx[(size_t)l*WSTRIDE + off] + Wrh[(size_t)l*WSTRIDE + off];
}

// hidden_out = [h0, out0 @ t=S-1, out1 @ t=S-1]
__global__ void k_tail(const float* __restrict__ hs,
                       const float* __restrict__ h0b,
                       const float* __restrict__ h1b,
                       float* __restrict__ out_h) {
    int b = blockIdx.x, n = threadIdx.x;
    size_t last = ((size_t)b*NS + (NS-1)) * (size_t)NN + n;
    out_h[b*3*NH + n]        = hs[b*3*NH + n];
    out_h[b*3*NH + 512 + n]  = h0b[last];
    out_h[b*3*NH + 1024 + n] = h1b[last];
}

// ---------------- fused GEMM ----------------
#define TBM 128
#define TBN 128
#define TBK 16
#define TM 8
#define TN 8

template<int EPI>
__global__ void __launch_bounds__(256) gemm_fused(
    const float* __restrict__ A, const float* __restrict__ W,
    float* __restrict__ C,
    const float* __restrict__ bias,
    const float* __restrict__ hterm,
    const float* __restrict__ hsrc, int hsrc_per_batch,
    const float* __restrict__ zbuf, const float* __restrict__ agbuf)
{
    __shared__ float As[TBK][TBM + 4];
    __shared__ float Bs[TBK][TBN];

    const int tid = threadIdx.x;
    const int bm = blockIdx.x * TBM;
    const int bn = blockIdx.y * TBN;
    const int tx = tid & 15;
    const int ty = tid >> 4;

    float acc[TM][TN];
    #pragma unroll
    for (int i = 0; i < TM; i++)
        #pragma unroll
        for (int j = 0; j < TN; j++) acc[i][j] = 0.f;

    const int a_row = tid >> 2;          // 0..63
    const int a_col = (tid & 3) * 4;     // 0,4,8,12
    const int b_row = tid >> 5;          // 0..7
    const int b_col = (tid & 31) * 4;    // 0..124

    const float* Abase = A + (size_t)bm * NK;

    for (int k0 = 0; k0 < NK; k0 += TBK) {
        #pragma unroll
        for (int i = 0; i < 2; i++) {
            int r = a_row + i * 64;
            float4 v = *(const float4*)(Abase + (size_t)r * NK + k0 + a_col);
            As[a_col + 0][r] = v.x;
            As[a_col + 1][r] = v.y;
            As[a_col + 2][r] = v.z;
            As[a_col + 3][r] = v.w;
        }
        #pragma unroll
        for (int i = 0; i < 2; i++) {
            int r = b_row + i * 8;
            float4 v = *(const float4*)(W + (size_t)(k0 + r) * NN + bn + b_col);
            *(float4*)&Bs[r][b_col] = v;
        }
        __syncthreads();
        #pragma unroll
        for (int k = 0; k < TBK; k++) {
            float ra[TM], rb[TN];
            #pragma unroll
            for (int i = 0; i < TM; i++) ra[i] = As[k][ty * TM + i];
            #pragma unroll
            for (int j = 0; j < TN; j++) rb[j] = Bs[k][tx * TN + j];
            #pragma unroll
            for (int i = 0; i < TM; i++)
                #pragma unroll
                for (int j = 0; j < TN; j++)
                    acc[i][j] = fmaf(ra[i], rb[j], acc[i][j]);
        }
        __syncthreads();
    }

    #pragma unroll
    for (int i = 0; i < TM; i++) {
        const int gm = bm + ty * TM + i;
        const int b  = gm >> 10;          // row -> batch (S = 1024)
        #pragma unroll
        for (int j = 0; j < TN; j++) {
            const int gn = bn + tx * TN + j;
            const size_t idx = (size_t)gm * NN + gn;
            float v = acc[i][j];
            if (EPI == 1) {
                v += bias[gn];
                if (hterm) v += hterm[b * NH + gn];
                C[idx] = 1.f / (1.f + __expf(-v));
            } else if (EPI == 2) {
                v += bias[gn];
                if (hterm) v += hterm[b * NH + gn];
                float r_ = 1.f / (1.f + __expf(-v));
                float hv = hsrc_per_batch ? hsrc[b * NH + gn] : hsrc[idx];
                C[idx] = r_ * hv;
            } else if (EPI == 3) {
                C[idx] = v + (bias ? bias[gn] : 0.f);
            } else {
                float g  = tanhf(v + agbuf[idx]);
                float zz = zbuf[idx];
                float hv = hsrc_per_batch ? hsrc[b * NH + gn] : hsrc[idx];
                C[idx] = zz * hv + (1.f - zz) * g;
            }
        }
    }
}

// ---------------- launch ----------------
extern "C" void kernel_launch(void* const* d_in, const int* in_sizes, int n_in,
                              void* d_out, int out_size) {
    const float* input = (const float*)d_in[0];
    const float* hs    = (const float*)d_in[1];
    const float* Wzx   = (const float*)d_in[2];
    const float* bzx   = (const float*)d_in[3];
    const float* Wzh   = (const float*)d_in[4];
    const float* Wrx   = (const float*)d_in[5];
    const float* brx   = (const float*)d_in[6];
    const float* Wrh   = (const float*)d_in[7];
    const float* Wgx   = (const float*)d_in[8];
    const float* bgx   = (const float*)d_in[9];
    const float* Wgh   = (const float*)d_in[10];
    const float* Wout  = (const float*)d_in[11];
    const float* bout  = (const float*)d_in[12];
    float* out = (float*)d_out;

    float *z, *ag, *rh, *h0b, *h1b, *h2b, *hz, *hr, *h0c, *wz, *wr;
    cudaGetSymbolAddress((void**)&z,   g_z);
    cudaGetSymbolAddress((void**)&ag,  g_ag);
    cudaGetSymbolAddress((void**)&rh,  g_rh);
    cudaGetSymbolAddress((void**)&h0b, g_h0b);
    cudaGetSymbolAddress((void**)&h1b, g_h1b);
    cudaGetSymbolAddress((void**)&h2b, g_h2b);
    cudaGetSymbolAddress((void**)&hz,  g_hz);
    cudaGetSymbolAddress((void**)&hr,  g_hr);
    cudaGetSymbolAddress((void**)&h0c, g_h0c);
    cudaGetSymbolAddress((void**)&wz,  g_wz);
    cudaGetSymbolAddress((void**)&wr,  g_wr);

    dim3 grid(NM / TBM, NN / TBN);   // (512, 4)
    dim3 blk(256);

    k_pre <<<dim3(64, 2), 512>>>(hs, Wzh, Wrh, hz, hr, h0c);
    k_comb<<<(2 * WSTRIDE + 255) / 256, 256>>>(Wzx, Wzh, Wrx, Wrh, wz, wr);

    // layer 0 (h = constant h0; x = input)
    gemm_fused<1><<<grid, blk>>>(input, Wzx,           z,   bzx,        hz,      nullptr, 0, nullptr, nullptr);
    gemm_fused<2><<<grid, blk>>>(input, Wrx,           rh,  brx,        hr,      h0c,     1, nullptr, nullptr);
    gemm_fused<3><<<grid, blk>>>(input, Wgx,           ag,  bgx,        nullptr, nullptr, 0, nullptr, nullptr);
    gemm_fused<4><<<grid, blk>>>(rh,    Wgh,           h0b, nullptr,    nullptr, h0c,     1, z, ag);

    // layer 1 (x == h == out0)
    gemm_fused<1><<<grid, blk>>>(h0b, wz,              z,   bzx + 512,  nullptr, nullptr, 0, nullptr, nullptr);
    gemm_fused<2><<<grid, blk>>>(h0b, wr,              rh,  brx + 512,  nullptr, h0b,     0, nullptr, nullptr);
    gemm_fused<3><<<grid, blk>>>(h0b, Wgx + WSTRIDE,   ag,  bgx + 512,  nullptr, nullptr, 0, nullptr, nullptr);
    gemm_fused<4><<<grid, blk>>>(rh,  Wgh + WSTRIDE,   h1b, nullptr,    nullptr, h0b,     0, z, ag);

    // layer 2 (x == h == out1)
    gemm_fused<1><<<grid, blk>>>(h1b, wz + WSTRIDE,    z,   bzx + 1024, nullptr, nullptr, 0, nullptr, nullptr);
    gemm_fused<2><<<grid, blk>>>(h1b, wr + WSTRIDE,    rh,  brx + 1024, nullptr, h1b,     0, nullptr, nullptr);
    gemm_fused<3><<<grid, blk>>>(h1b, Wgx + 2*WSTRIDE, ag,  bgx + 1024, nullptr, nullptr, 0, nullptr, nullptr);
    gemm_fused<4><<<grid, blk>>>(rh,  Wgh + 2*WSTRIDE, h2b, nullptr,    nullptr, h1b,     0, z, ag);

    // output projection
    gemm_fused<3><<<grid, blk>>>(h2b, Wout, out, bout, nullptr, nullptr, 0, nullptr, nullptr);

    // hidden_out tail
    k_tail<<<64, 512>>>(hs, h0b, h1b, out + (size_t)NM * NN);
}

// round 3
// speedup vs baseline: 1.9664x; 1.9664x over previous
#include <cuda_runtime.h>
#include <cuda_bf16.h>
#include <cstdint>

// ---------------- problem constants ----------------
#define NB 64
#define NS 1024
#define NH 512
#define NM (NB*NS)          // 65536 rows
#define NN 512
#define WSTRIDE (512*512)
#define PLANE ((size_t)NM*NN)

// GEMM tiling (legacy mma.sync path; compute_100-safe)
#define BM 128
#define BN 128
#define BK 32
#define KPRIME 1536         // 3 * 512
#define ITERS (KPRIME/BK)   // 48
#define ROWE 40             // padded row length in bf16 elems (80 bytes)
#define ROWB 80
#define A_SLOT (BM*ROWB)    // 10240
#define B_SLOT (BN*ROWB)    // 10240
#define SLOT (A_SLOT+B_SLOT)
#define NSLOTS 4
#define SMEM_BYTES (NSLOTS*SLOT)   // 81920

// ---------------- device scratch ----------------
__device__ __nv_bfloat16 g_act_hi[(size_t)5*NM*NN];  // 0=X 1=rh 2=h0 3=h1 4=h2
__device__ __nv_bfloat16 g_act_lo[(size_t)5*NM*NN];
__device__ __nv_bfloat16 g_wt_hi[(size_t)13*WSTRIDE]; // B^T [N,K] per slot
__device__ __nv_bfloat16 g_wt_lo[(size_t)13*WSTRIDE];
__device__ float g_z [PLANE];
__device__ float g_ag[PLANE];
__device__ float g_hz [NB*NH];
__device__ float g_hr [NB*NH];
__device__ float g_h0c[NB*NH];

// ---------------- helpers ----------------
__device__ __forceinline__ uint32_t smem_u32(const void* p) {
    uint32_t a;
    asm("{ .reg .u64 t; cvta.to.shared.u64 t, %1; cvt.u32.u64 %0, t; }" : "=r"(a) : "l"(p));
    return a;
}
__device__ __forceinline__ void cp_async16(uint32_t dst, const void* src) {
    asm volatile("cp.async.cg.shared.global [%0], [%1], 16;" :: "r"(dst), "l"(src) : "memory");
}
__device__ __forceinline__ void cp_commit() { asm volatile("cp.async.commit_group;" ::: "memory"); }
__device__ __forceinline__ void cp_wait2()  { asm volatile("cp.async.wait_group 2;" ::: "memory"); }

__device__ __forceinline__ void ldmatrix4(uint32_t& r0, uint32_t& r1, uint32_t& r2, uint32_t& r3, uint32_t addr) {
    asm volatile("ldmatrix.sync.aligned.m8n8.x4.shared.b16 {%0,%1,%2,%3}, [%4];"
                 : "=r"(r0), "=r"(r1), "=r"(r2), "=r"(r3) : "r"(addr));
}
__device__ __forceinline__ void mma_bf16(float* d, const uint32_t* a, const uint32_t* b) {
    asm volatile("mma.sync.aligned.m16n8k16.row.col.f32.bf16.bf16.f32 "
        "{%0,%1,%2,%3}, {%4,%5,%6,%7}, {%8,%9}, {%0,%1,%2,%3};"
        : "+f"(d[0]), "+f"(d[1]), "+f"(d[2]), "+f"(d[3])
        : "r"(a[0]), "r"(a[1]), "r"(a[2]), "r"(a[3]), "r"(b[0]), "r"(b[1]));
}
__device__ __forceinline__ void split2(float v, __nv_bfloat16& hi, __nv_bfloat16& lo) {
    hi = __float2bfloat16(v);
    lo = __float2bfloat16(v - __bfloat162float(hi));
}

// ---------------- prep kernels ----------------
__global__ void k_split(const float4* __restrict__ x,
                        __nv_bfloat16* __restrict__ hi, __nv_bfloat16* __restrict__ lo) {
    size_t i = (size_t)blockIdx.x * blockDim.x + threadIdx.x;
    float4 v = x[i];
    float a[4] = {v.x, v.y, v.z, v.w};
    #pragma unroll
    for (int j = 0; j < 4; j++) {
        __nv_bfloat16 h, l; split2(a[j], h, l);
        hi[4*i + j] = h; lo[4*i + j] = l;
    }
}

// Transpose + (optional add) + split:  out[n][k] = W[k][n] (+ W2[k][n])
__global__ void k_wprep(const float* __restrict__ W, const float* __restrict__ W2,
                        __nv_bfloat16* __restrict__ hi, __nv_bfloat16* __restrict__ lo) {
    __shared__ float t[32][33];
    int k0 = blockIdx.y * 32, n0 = blockIdx.x * 32;
    for (int r = threadIdx.y; r < 32; r += 8) {
        float v = W[(size_t)(k0 + r) * 512 + n0 + threadIdx.x];
        if (W2) v += W2[(size_t)(k0 + r) * 512 + n0 + threadIdx.x];
        t[r][threadIdx.x] = v;
    }
    __syncthreads();
    for (int r = threadIdx.y; r < 32; r += 8) {
        float v = t[threadIdx.x][r];
        __nv_bfloat16 h, l; split2(v, h, l);
        hi[(size_t)(n0 + r) * 512 + k0 + threadIdx.x] = h;
        lo[(size_t)(n0 + r) * 512 + k0 + threadIdx.x] = l;
    }
}

__global__ void k_pre(const float* __restrict__ hs,
                      const float* __restrict__ Wzh0, const float* __restrict__ Wrh0,
                      float* __restrict__ hz, float* __restrict__ hr, float* __restrict__ h0c) {
    __shared__ float h0s[512];
    int b = blockIdx.x, n = threadIdx.x;
    float h0v = hs[b*3*NH + n];
    h0s[n] = h0v;
    if (blockIdx.y == 0) h0c[b*NH + n] = h0v;
    __syncthreads();
    const float* W = blockIdx.y ? Wrh0 : Wzh0;
    float acc = 0.f;
    #pragma unroll 8
    for (int k = 0; k < 512; k++) acc = fmaf(h0s[k], W[k*512 + n], acc);
    (blockIdx.y ? hr : hz)[b*NH + n] = acc;
}

__global__ void k_tail(const float* __restrict__ hs,
                       const __nv_bfloat16* __restrict__ h0hi, const __nv_bfloat16* __restrict__ h0lo,
                       const __nv_bfloat16* __restrict__ h1hi, const __nv_bfloat16* __restrict__ h1lo,
                       float* __restrict__ out_h) {
    int b = blockIdx.x, n = threadIdx.x;
    size_t last = ((size_t)b*NS + (NS-1)) * (size_t)NN + n;
    out_h[b*3*NH + n]        = hs[b*3*NH + n];
    out_h[b*3*NH + 512 + n]  = __bfloat162float(h0hi[last]) + __bfloat162float(h0lo[last]);
    out_h[b*3*NH + 1024 + n] = __bfloat162float(h1hi[last]) + __bfloat162float(h1lo[last]);
}

// ---------------- bf16x3 HMMA GEMM with fused GRU epilogue ----------------
// C[M,N] = Ahi@Bhi^T + Ahi@Blo^T + Alo@Bhi^T  (K' = 1536, seg-selected planes)
// EPI 1: z = sigmoid(acc + bias + hterm[b])            -> Cf
// EPI 2: r = sigmoid(acc + bias + hterm[b]); r*hv      -> Chi/Clo
// EPI 3: acc + bias                                     -> Cf
// EPI 4: g = tanh(acc + ag); z*hv + (1-z)*g             -> Chi/Clo
template<int EPI>
__global__ void __launch_bounds__(256) gemm_mma(
    const __nv_bfloat16* __restrict__ Ahi, const __nv_bfloat16* __restrict__ Alo,
    const __nv_bfloat16* __restrict__ Bhi, const __nv_bfloat16* __restrict__ Blo,
    float* __restrict__ Cf,
    __nv_bfloat16* __restrict__ Chi, __nv_bfloat16* __restrict__ Clo,
    const float* __restrict__ bias, const float* __restrict__ hterm,
    const float* __restrict__ h0c,
    const __nv_bfloat16* __restrict__ hvhi, const __nv_bfloat16* __restrict__ hvlo,
    const float* __restrict__ zb, const float* __restrict__ agb)
{
    extern __shared__ char smem_raw[];
    const uint32_t base = smem_u32(smem_raw);
    const int tid = threadIdx.x;
    const int lane = tid & 31;
    const int w = tid >> 5;
    const int wr = w >> 2;          // 0..1  (64 rows each)
    const int wc = w & 3;           // 0..3  (32 cols each)
    const int bm = blockIdx.y * BM;
    const int bn = blockIdx.x * BN;

    float c[4][4][4];
    #pragma unroll
    for (int i = 0; i < 4; i++)
        #pragma unroll
        for (int j = 0; j < 4; j++)
            #pragma unroll
            for (int e = 0; e < 4; e++) c[i][j][e] = 0.f;

    // per-lane ldmatrix offsets (bytes) within a slot
    const uint32_t a_lm = ((wr*64 + ((lane>>3)&1)*8 + (lane&7)) * ROWE + (lane>>4)*8) * 2;
    const uint32_t b_lm = ((wc*32 + (lane>>4)*8 + (lane&7)) * ROWE + ((lane>>3)&1)*8) * 2;

    // cp.async chunk mapping (16B chunks; row = ch/4, seg = ch%4)
    auto issue = [&](int cidx) {
        const int slot = cidx & 3;
        const __nv_bfloat16* ap = (cidx < 32) ? Ahi : Alo;
        const __nv_bfloat16* bp = ((cidx >> 4) == 1) ? Blo : Bhi;
        const int ko = (cidx & 15) * BK;
        const uint32_t sA = base + slot * SLOT;
        const uint32_t sB = sA + A_SLOT;
        #pragma unroll
        for (int i = 0; i < 2; i++) {
            int ch = tid + i * 256;
            int row = ch >> 2, cs = ch & 3;
            cp_async16(sA + row * ROWB + cs * 16,
                       ap + (size_t)(bm + row) * 512 + ko + cs * 8);
        }
        #pragma unroll
        for (int i = 0; i < 2; i++) {
            int ch = tid + i * 256;
            int row = ch >> 2, cs = ch & 3;
            cp_async16(sB + row * ROWB + cs * 16,
                       bp + (size_t)(bn + row) * 512 + ko + cs * 8);
        }
    };

    issue(0); cp_commit();
    issue(1); cp_commit();
    issue(2); cp_commit();

    for (int it = 0; it < ITERS; it++) {
        cp_wait2();
        __syncthreads();
        if (it + 3 < ITERS) issue(it + 3);
        cp_commit();

        const int slot = it & 3;
        const uint32_t sA = base + slot * SLOT;
        const uint32_t sB = sA + A_SLOT;
        #pragma unroll
        for (int kh = 0; kh < 2; kh++) {
            const uint32_t koffB = kh * 32;   // 16 elems * 2B
            uint32_t a[4][4], b[4][2];
            #pragma unroll
            for (int mt = 0; mt < 4; mt++)
                ldmatrix4(a[mt][0], a[mt][1], a[mt][2], a[mt][3],
                          sA + a_lm + mt * (16*ROWB) + koffB);
            #pragma unroll
            for (int np = 0; np < 2; np++) {
                uint32_t r0, r1, r2, r3;
                ldmatrix4(r0, r1, r2, r3, sB + b_lm + np * (16*ROWB) + koffB);
                b[np*2][0] = r0; b[np*2][1] = r1;
                b[np*2+1][0] = r2; b[np*2+1][1] = r3;
            }
            #pragma unroll
            for (int mt = 0; mt < 4; mt++)
                #pragma unroll
                for (int nt = 0; nt < 4; nt++)
                    mma_bf16(c[mt][nt], a[mt], b[nt]);
        }
    }

    // ---- fused epilogue (registers only) ----
    const int rbase = bm + wr * 64;
    const int cbase = bn + wc * 32;
    #pragma unroll
    for (int mt = 0; mt < 4; mt++) {
        #pragma unroll
        for (int er = 0; er < 2; er++) {
            const int gm = rbase + mt*16 + (lane >> 2) + er*8;
            const int bb = gm >> 10;
            #pragma unroll
            for (int nt = 0; nt < 4; nt++) {
                #pragma unroll
                for (int ec = 0; ec < 2; ec++) {
                    const int gn = cbase + nt*8 + (lane & 3)*2 + ec;
                    const size_t idx = (size_t)gm * NN + gn;
                    float v = c[mt][nt][er*2 + ec];
                    if (EPI == 1) {
                        v += bias[gn];
                        if (hterm) v += hterm[bb * NH + gn];
                        Cf[idx] = 1.f / (1.f + __expf(-v));
                    } else if (EPI == 2) {
                        v += bias[gn];
                        if (hterm) v += hterm[bb * NH + gn];
                        float r_ = 1.f / (1.f + __expf(-v));
                        float hv = h0c ? h0c[bb * NH + gn]
                                       : __bfloat162float(hvhi[idx]) + __bfloat162float(hvlo[idx]);
                        float o = r_ * hv;
                        __nv_bfloat16 h, l; split2(o, h, l);
                        Chi[idx] = h; Clo[idx] = l;
                    } else if (EPI == 3) {
                        Cf[idx] = v + bias[gn];
                    } else {
                        float g = tanhf(v + agb[idx]);
                        float z = zb[idx];
                        float hv = h0c ? h0c[bb * NH + gn]
                                       : __bfloat162float(hvhi[idx]) + __bfloat162float(hvlo[idx]);
                        float o = z * hv + (1.f - z) * g;
                        __nv_bfloat16 h, l; split2(o, h, l);
                        Chi[idx] = h; Clo[idx] = l;
                    }
                }
            }
        }
    }
}

// ---------------- host ----------------
extern "C" void kernel_launch(void* const* d_in, const int* in_sizes, int n_in,
                              void* d_out, int out_size) {
    const float* input = (const float*)d_in[0];
    const float* hs    = (const float*)d_in[1];
    const float* Wzx   = (const float*)d_in[2];
    const float* bzx   = (const float*)d_in[3];
    const float* Wzh   = (const float*)d_in[4];
    const float* Wrx   = (const float*)d_in[5];
    const float* brx   = (const float*)d_in[6];
    const float* Wrh   = (const float*)d_in[7];
    const float* Wgx   = (const float*)d_in[8];
    const float* bgx   = (const float*)d_in[9];
    const float* Wgh   = (const float*)d_in[10];
    const float* Wout  = (const float*)d_in[11];
    const float* bout  = (const float*)d_in[12];
    float* out = (float*)d_out;

    __nv_bfloat16 *ahi, *alo, *whi, *wlo;
    float *z, *ag, *hz, *hr, *h0c;
    cudaGetSymbolAddress((void**)&ahi, g_act_hi);
    cudaGetSymbolAddress((void**)&alo, g_act_lo);
    cudaGetSymbolAddress((void**)&whi, g_wt_hi);
    cudaGetSymbolAddress((void**)&wlo, g_wt_lo);
    cudaGetSymbolAddress((void**)&z,   g_z);
    cudaGetSymbolAddress((void**)&ag,  g_ag);
    cudaGetSymbolAddress((void**)&hz,  g_hz);
    cudaGetSymbolAddress((void**)&hr,  g_hr);
    cudaGetSymbolAddress((void**)&h0c, g_h0c);

    cudaFuncSetAttribute(gemm_mma<1>, cudaFuncAttributeMaxDynamicSharedMemorySize, SMEM_BYTES);
    cudaFuncSetAttribute(gemm_mma<2>, cudaFuncAttributeMaxDynamicSharedMemorySize, SMEM_BYTES);
    cudaFuncSetAttribute(gemm_mma<3>, cudaFuncAttributeMaxDynamicSharedMemorySize, SMEM_BYTES);
    cudaFuncSetAttribute(gemm_mma<4>, cudaFuncAttributeMaxDynamicSharedMemorySize, SMEM_BYTES);

    // ---- prep ----
    k_split<<<PLANE/4/256, 256>>>((const float4*)input, ahi, alo);      // X -> plane 0
    k_pre<<<dim3(64,2), 512>>>(hs, Wzh, Wrh, hz, hr, h0c);
    dim3 wg(16,16), wb(32,8);
    k_wprep<<<wg,wb>>>(Wzx,            nullptr,        whi + 0*WSTRIDE,  wlo + 0*WSTRIDE);
    k_wprep<<<wg,wb>>>(Wrx,            nullptr,        whi + 1*WSTRIDE,  wlo + 1*WSTRIDE);
    k_wprep<<<wg,wb>>>(Wgx,            nullptr,        whi + 2*WSTRIDE,  wlo + 2*WSTRIDE);
    k_wprep<<<wg,wb>>>(Wgh,            nullptr,        whi + 3*WSTRIDE,  wlo + 3*WSTRIDE);
    k_wprep<<<wg,wb>>>(Wzx + WSTRIDE,  Wzh + WSTRIDE,  whi + 4*WSTRIDE,  wlo + 4*WSTRIDE);
    k_wprep<<<wg,wb>>>(Wrx + WSTRIDE,  Wrh + WSTRIDE,  whi + 5*WSTRIDE,  wlo + 5*WSTRIDE);
    k_wprep<<<wg,wb>>>(Wgx + WSTRIDE,  nullptr,        whi + 6*WSTRIDE,  wlo + 6*WSTRIDE);
    k_wprep<<<wg,wb>>>(Wgh + WSTRIDE,  nullptr,        whi + 7*WSTRIDE,  wlo + 7*WSTRIDE);
    k_wprep<<<wg,wb>>>(Wzx + 2*WSTRIDE,Wzh + 2*WSTRIDE,whi + 8*WSTRIDE,  wlo + 8*WSTRIDE);
    k_wprep<<<wg,wb>>>(Wrx + 2*WSTRIDE,Wrh + 2*WSTRIDE,whi + 9*WSTRIDE,  wlo + 9*WSTRIDE);
    k_wprep<<<wg,wb>>>(Wgx + 2*WSTRIDE,nullptr,        whi + 10*WSTRIDE, wlo + 10*WSTRIDE);
    k_wprep<<<wg,wb>>>(Wgh + 2*WSTRIDE,nullptr,        whi + 11*WSTRIDE, wlo + 11*WSTRIDE);
    k_wprep<<<wg,wb>>>(Wout,           nullptr,        whi + 12*WSTRIDE, wlo + 12*WSTRIDE);

    dim3 grid(NN / BN, NM / BM);   // (4, 512): N fastest -> A reuse in L2
    dim3 blk(256);
    __nv_bfloat16* AH[5]; __nv_bfloat16* AL[5];
    for (int i = 0; i < 5; i++) { AH[i] = ahi + (size_t)i*PLANE; AL[i] = alo + (size_t)i*PLANE; }
    #define WSLOT(s) (whi + (size_t)(s)*WSTRIDE), (wlo + (size_t)(s)*WSTRIDE)

    // ---- layer 0 (h = const h0; x = input, plane 0) ----
    gemm_mma<1><<<grid,blk,SMEM_BYTES>>>(AH[0],AL[0], WSLOT(0),  z,  nullptr,nullptr, bzx,      hz,  nullptr, nullptr,nullptr, nullptr,nullptr);
    gemm_mma<2><<<grid,blk,SMEM_BYTES>>>(AH[0],AL[0], WSLOT(1),  nullptr, AH[1],AL[1], brx,     hr,  h0c,     nullptr,nullptr, nullptr,nullptr);
    gemm_mma<3><<<grid,blk,SMEM_BYTES>>>(AH[0],AL[0], WSLOT(2),  ag, nullptr,nullptr, bgx,      nullptr,nullptr, nullptr,nullptr, nullptr,nullptr);
    gemm_mma<4><<<grid,blk,SMEM_BYTES>>>(AH[1],AL[1], WSLOT(3),  nullptr, AH[2],AL[2], nullptr, nullptr, h0c, nullptr,nullptr, z, ag);
    // ---- layer 1 (x == h == plane 2) ----
    gemm_mma<1><<<grid,blk,SMEM_BYTES>>>(AH[2],AL[2], WSLOT(4),  z,  nullptr,nullptr, bzx+512,  nullptr,nullptr, nullptr,nullptr, nullptr,nullptr);
    gemm_mma<2><<<grid,blk,SMEM_BYTES>>>(AH[2],AL[2], WSLOT(5),  nullptr, AH[1],AL[1], brx+512, nullptr, nullptr, AH[2],AL[2], nullptr,nullptr);
    gemm_mma<3><<<grid,blk,SMEM_BYTES>>>(AH[2],AL[2], WSLOT(6),  ag, nullptr,nullptr, bgx+512,  nullptr,nullptr, nullptr,nullptr, nullptr,nullptr);
    gemm_mma<4><<<grid,blk,SMEM_BYTES>>>(AH[1],AL[1], WSLOT(7),  nullptr, AH[3],AL[3], nullptr, nullptr, nullptr, AH[2],AL[2], z, ag);
    // ---- layer 2 (x == h == plane 3) ----
    gemm_mma<1><<<grid,blk,SMEM_BYTES>>>(AH[3],AL[3], WSLOT(8),  z,  nullptr,nullptr, bzx+1024, nullptr,nullptr, nullptr,nullptr, nullptr,nullptr);
    gemm_mma<2><<<grid,blk,SMEM_BYTES>>>(AH[3],AL[3], WSLOT(9),  nullptr, AH[1],AL[1], brx+1024, nullptr, nullptr, AH[3],AL[3], nullptr,nullptr);
    gemm_mma<3><<<grid,blk,SMEM_BYTES>>>(AH[3],AL[3], WSLOT(10), ag, nullptr,nullptr, bgx+1024, nullptr,nullptr, nullptr,nullptr, nullptr,nullptr);
    gemm_mma<4><<<grid,blk,SMEM_BYTES>>>(AH[1],AL[1], WSLOT(11), nullptr, AH[4],AL[4], nullptr, nullptr, nullptr, AH[3],AL[3], z, ag);
    // ---- output projection ----
    gemm_mma<3><<<grid,blk,SMEM_BYTES>>>(AH[4],AL[4], WSLOT(12), out, nullptr,nullptr, bout,    nullptr,nullptr, nullptr,nullptr, nullptr,nullptr);

    k_tail<<<64, 512>>>(hs, AH[2],AL[2], AH[3],AL[3], out + PLANE);
}